// round 7
// baseline (speedup 1.0000x reference)
#include <cuda_runtime.h>
#include <cstdint>

#define NFFT   512
#define HOPSZ  160
#define PADN   256
#define BVAL   32
#define TVAL   1024
#define FBINS  257
#define LTRIM  163680                  // (TVAL-1)*HOPSZ
#define OUTLEN 164192                  // NFFT + HOPSZ*(TVAL-1)
#define NITER  32
#define NFRAMES (BVAL*TVAL)            // 32768
#define PI_F 3.14159265358979323846f
#define RSQ2 0.70710678118654752440f

#define FR_PER_BLK 16
#define BLK_SPAN   (HOPSZ*(FR_PER_BLK-1) + NFFT)   // 2912
#define BLK_STRIDE (HOPSZ*FR_PER_BLK)              // 2560
#define OVL        (NFFT - HOPSZ)                  // 352 boundary strip
#define SPB        (TVAL / FR_PER_BLK)             // 64 blocks per batch

// ---------------- scratch (device globals; no allocation allowed) ------------
__device__ float4 g_ya4[(BVAL * OUTLEN) / 4];      // waveform ping, 21 MB
__device__ float4 g_yb4[(BVAL * OUTLEN) / 4];      // waveform pong, 21 MB
#define G_YA ((float*)g_ya4)
#define G_YB ((float*)g_yb4)
__device__ float  g_invwsq[OUTLEN];                // NOLA 1/wsq (guarded)
__device__ float2 g_tw[256];                       // e^{+2*pi*i*k/256}
__device__ float2 g_pk[FBINS];                     // (cos(pi k/256), sin(pi k/256))

__device__ __forceinline__ float2 cmulf(float2 a, float2 b) {
    return make_float2(a.x * b.x - a.y * b.y, a.x * b.y + a.y * b.x);
}
__device__ __forceinline__ float2 cadd(float2 a, float2 b) {
    return make_float2(a.x + b.x, a.y + b.y);
}
__device__ __forceinline__ float2 csub(float2 a, float2 b) {
    return make_float2(a.x - b.x, a.y - b.y);
}
template <int SGN>
__device__ __forceinline__ float2 cmuli(float2 a) {   // SGN * i * a
    return (SGN > 0) ? make_float2(-a.y, a.x) : make_float2(a.y, -a.x);
}

// padded smem index: +1 float2 every 16 to break stride-8/16 conflicts
#define IDXP(i) ((i) + ((i) >> 4))
#define SBUF 272

// ---------------------------------------------------------------------------
// 256-pt complex FFT, one warp per transform, 8 complex points per lane.
// Input:  v[j] = x[l + 32*j] (natural order); Output: v[j] = X[j + 8*brev5(l)]
// SGN = -1 forward, +1 inverse (unnormalized)
// ---------------------------------------------------------------------------
template <int SGN>
__device__ __forceinline__ void fft256_warp(float2 v[8], int l) {
    float2 t0 = v[0], t1 = v[4], t2 = v[2], t3 = v[6];
    float2 t4 = v[1], t5 = v[5], t6 = v[3], t7 = v[7];
    float2 a0 = cadd(t0, t1), a1 = csub(t0, t1);
    float2 a2 = cadd(t2, t3), a3 = csub(t2, t3);
    float2 a4 = cadd(t4, t5), a5 = csub(t4, t5);
    float2 a6 = cadd(t6, t7), a7 = csub(t6, t7);
    float2 i3 = cmuli<SGN>(a3), i7 = cmuli<SGN>(a7);
    float2 b0 = cadd(a0, a2), b2 = csub(a0, a2);
    float2 b1 = cadd(a1, i3), b3 = csub(a1, i3);
    float2 b4 = cadd(a4, a6), b6 = csub(a4, a6);
    float2 b5 = cadd(a5, i7), b7 = csub(a5, i7);
    float2 u1 = make_float2(RSQ2 * (b5.x - (float)SGN * b5.y),
                            RSQ2 * (b5.y + (float)SGN * b5.x));
    float2 u2 = cmuli<SGN>(b6);
    float2 u3 = make_float2(-RSQ2 * (b7.x + (float)SGN * b7.y),
                             RSQ2 * ((float)SGN * b7.x - b7.y));
    v[0] = cadd(b0, b4);  v[4] = csub(b0, b4);
    v[1] = cadd(b1, u1);  v[5] = csub(b1, u1);
    v[2] = cadd(b2, u2);  v[6] = csub(b2, u2);
    v[3] = cadd(b3, u3);  v[7] = csub(b3, u3);

    float2 w1 = g_tw[l];
    if (SGN < 0) w1.y = -w1.y;
    float2 w = w1;
    v[1] = cmulf(v[1], w);
#pragma unroll
    for (int k1 = 2; k1 < 8; k1++) {
        w = cmulf(w, w1);
        v[k1] = cmulf(v[k1], w);
    }

#pragma unroll
    for (int s = 0; s < 5; s++) {
        const int m = 16 >> s;
        const bool hi = (l & m) != 0;
        int tidx = (l & (m - 1)) << s;
        float2 tw = g_tw[tidx << 3];
        if (SGN < 0) tw.y = -tw.y;
        if (!hi) tw = make_float2(1.f, 0.f);
        const float p = hi ? -1.f : 1.f;
#pragma unroll
        for (int j = 0; j < 8; j++) {
            float2 o = v[j];
            float2 t;
            t.x = __shfl_xor_sync(0xffffffffu, o.x, m);
            t.y = __shfl_xor_sync(0xffffffffu, o.y, m);
            float2 q = make_float2(t.x + p * o.x, t.y + p * o.y);
            v[j] = cmulf(q, tw);
        }
    }
}

__device__ __forceinline__ int brev5(int l) { return (int)(__brev((unsigned)l) >> 27); }

// ---------------------------------------------------------------------------
__global__ void k_tables() {
    int k = threadIdx.x;
    if (k < 256) {
        float a = (2.0f * PI_F) * (float)k / 256.0f;
        g_tw[k] = make_float2(cosf(a), sinf(a));
    }
    if (k < FBINS) {
        float b = PI_F * (float)k / 256.0f;
        g_pk[k] = make_float2(cosf(b), sinf(b));
    }
}

__global__ void k_invwsq(const float* __restrict__ win) {
    int i = blockIdx.x * blockDim.x + threadIdx.x;
    if (i >= OUTLEN) return;
    int tmax = i / HOPSZ;             if (tmax > TVAL - 1) tmax = TVAL - 1;
    int tmin = (i - (NFFT - 1) + HOPSZ - 1) / HOPSZ;  if (tmin < 0) tmin = 0;
    float s = 0.f;
    for (int t = tmin; t <= tmax; t++) {
        int n = i - t * HOPSZ;
        if (n >= 0 && n < NFFT) { float w = win[n]; s += w * w; }
    }
    g_invwsq[i] = (s > 1e-11f) ? (1.0f / s) : 1.0f;
}

// zero only the OLA boundary strips: 352 floats at q*2560, q=0..64, per batch
#define NSTRIP (SPB + 1)                        // 65
#define STRIP4 (OVL / 4)                        // 88 float4 per strip
__global__ void k_zero_strips(float* __restrict__ y) {
    int i = blockIdx.x * blockDim.x + threadIdx.x;
    const int total = BVAL * NSTRIP * STRIP4;   // 183040
    if (i >= total) return;
    int b = i / (NSTRIP * STRIP4);
    int r = i - b * (NSTRIP * STRIP4);
    int q = r / STRIP4;
    int o = r - q * STRIP4;
    size_t idx = (size_t)b * OUTLEN + (size_t)q * BLK_STRIDE + o * 4;
    *(float4*)(y + idx) = make_float4(0.f, 0.f, 0.f, 0.f);
}

// ---------------------------------------------------------------------------
// shared epilogue: inverse FFT (v holds packed Z' natural order), bitrev undo,
// windowed block-OLA, interior stores + boundary atomics
// ---------------------------------------------------------------------------
__device__ __forceinline__ void istft_tail(float2 v[8], float2 (*sw)[SBUF],
                                           float* ola, int wid, int l,
                                           const float* win, float* yb) {
    fft256_warp<1>(v, l);   // inverse, unnormalized
    const int r8 = brev5(l) << 3;
#pragma unroll
    for (int j = 0; j < 8; j++) sw[wid][IDXP(j + r8)] = v[j];
    __syncwarp();

    float* olap = ola + wid * HOPSZ;
    const float2* w2p = (const float2*)win;
#pragma unroll
    for (int j = 0; j < 8; j++) {
        int m = l + (j << 5);
        float2 z = sw[wid][IDXP(m)];
        float2 w = w2p[m];
        atomicAdd(olap + 2 * m,     z.x * (1.0f / 256.0f) * w.x);
        atomicAdd(olap + 2 * m + 1, z.y * (1.0f / 256.0f) * w.y);
    }
    __syncthreads();

    const float4* oi = (const float4*)(ola + OVL);
    float4* yi = (float4*)(yb + OVL);
    for (int i = threadIdx.x; i < (BLK_STRIDE - OVL) / 4; i += 512)
        yi[i] = oi[i];
    for (int i = threadIdx.x; i < 2 * OVL; i += 512) {
        int idx = (i < OVL) ? i : (BLK_STRIDE - OVL + i);
        atomicAdd(yb + idx, ola[idx]);
    }
}

// ---------------------------------------------------------------------------
// Init: spec = mag * exp(i*angles) -> irfft -> window -> block OLA into y
// ---------------------------------------------------------------------------
__global__ __launch_bounds__(512) void k_istft_init(const float* __restrict__ mag,
                                                    const float* __restrict__ ang,
                                                    const float* __restrict__ win,
                                                    float* __restrict__ y) {
    __shared__ float2 sw[FR_PER_BLK][SBUF];
    __shared__ float4 ola4[BLK_SPAN / 4];
    float* ola = (float*)ola4;

    const int wid = threadIdx.x >> 5;
    const int l   = threadIdx.x & 31;
    const int s   = blockIdx.x & (SPB - 1);
    const int b   = blockIdx.x >> 6;
    const int t0  = s << 4;
    const int frame = (b << 10) + t0 + wid;
    const float* magp = mag + (size_t)frame * FBINS;
    const float* angp = ang + (size_t)frame * FBINS;

    for (int i = threadIdx.x; i < BLK_SPAN; i += 512) ola[i] = 0.f;
    __syncthreads();

    float2 v[8];
#pragma unroll
    for (int j = 0; j < 8; j++) {
        int k  = l + (j << 5);
        int kr = 256 - k;
        float sk, ck, sr, cr;
        sincosf(angp[k],  &sk, &ck);
        sincosf(angp[kr], &sr, &cr);
        float mk = magp[k], mr = magp[kr];
        float Xkx = mk * ck, Xky = mk * sk;
        float Xcx = mr * cr, Xcy = -mr * sr;          // conj(X[256-k])
        if (k == 0) { Xky = 0.f; Xcy = 0.f; }
        float Zex = 0.5f * (Xkx + Xcx), Zey = 0.5f * (Xky + Xcy);
        float Bx  = 0.5f * (Xkx - Xcx), By  = 0.5f * (Xky - Xcy);
        float2 e = g_pk[k];
        float Qx = Bx * e.x - By * e.y;
        float Qy = Bx * e.y + By * e.x;
        v[j] = make_float2(Zex - Qy, Zey + Qx);
    }
    istft_tail(v, sw, ola, wid, l, win,
               y + (size_t)b * OUTLEN + (size_t)t0 * HOPSZ);
}

// ---------------------------------------------------------------------------
// Fused Griffin-Lim step: y_src -> stft -> phase -> mag*phase -> istft -> y_dst
// ---------------------------------------------------------------------------
__device__ __forceinline__ float sample_at(const float* yb, int i) {
    int j = i - PADN;
    j = (j < 0) ? -j : j;
    if (j >= LTRIM) j = 2 * LTRIM - 2 - j;
    int idx = j + PADN;
    return yb[idx] * g_invwsq[idx];
}

__device__ __forceinline__ float2 scaled_norm(float x, float y, float m) {
    float m2 = x * x + y * y;
    if (m2 < 1e-30f) return make_float2(m, 0.f);  // atan2(0,0)=0 -> phase (1,0)
    float inv = m * rsqrtf(m2);
    return make_float2(x * inv, y * inv);
}

__global__ __launch_bounds__(512) void k_gl_step(const float* __restrict__ mag,
                                                 const float* __restrict__ win,
                                                 const float* __restrict__ ysrc,
                                                 float* __restrict__ ydst) {
    __shared__ float2 sw[FR_PER_BLK][SBUF];     // 34.8 KB
    __shared__ float4 ola4[BLK_SPAN / 4];       // 11.6 KB
    float* ola = (float*)ola4;

    const int wid = threadIdx.x >> 5;
    const int l   = threadIdx.x & 31;
    const int s   = blockIdx.x & (SPB - 1);
    const int b   = blockIdx.x >> 6;
    const int t0  = s << 4;
    const int frame = (b << 10) + t0 + wid;
    const float* magp = mag + (size_t)frame * FBINS;
    const float* ysb  = ysrc + (size_t)b * OUTLEN;
    const int i0 = (t0 + wid) * HOPSZ;

    for (int i = threadIdx.x; i < BLK_SPAN; i += 512) ola[i] = 0.f;
    __syncthreads();

    // ---- STFT gather + forward FFT ----
    float2 v[8];
#pragma unroll
    for (int j = 0; j < 8; j++) {
        int m  = l + (j << 5);
        int n0 = 2 * m;
        float x0 = sample_at(ysb, i0 + n0);
        float x1 = sample_at(ysb, i0 + n0 + 1);
        float2 w = ((const float2*)win)[m];
        v[j] = make_float2(x0 * w.x, x1 * w.y);
    }
    fft256_warp<-1>(v, l);   // forward

    const int r8 = brev5(l) << 3;
#pragma unroll
    for (int j = 0; j < 8; j++) sw[wid][IDXP(j + r8)] = v[j];
    __syncwarp();

    // ---- unpack pair + phase + re-magnitude + inverse pack, in registers ----
    // X[k] = Ze + Zo*W^k = S ; conj(X[256-k]) = Ze - Zo*W^k = D
    // Z'[k] = Pe + i*(B*e),  Pe=(A+C)/2, B=(A-C)/2, A=mk*S/|S|, C=mr*D/|D|
#pragma unroll
    for (int j = 0; j < 8; j++) {
        int k = l + (j << 5);
        if (k == 0) {
            float2 Z0 = sw[wid][IDXP(0)];
            float X0 = Z0.x + Z0.y;       // X[0]   (real)
            float XN = Z0.x - Z0.y;       // X[256] (real)
            float s0 = (X0 * X0 < 1e-30f) ? 1.f : X0 * rsqrtf(X0 * X0);
            float sN = (XN * XN < 1e-30f) ? 1.f : XN * rsqrtf(XN * XN);
            float A = magp[0] * s0;
            float C = magp[256] * sN;
            v[j] = make_float2(0.5f * (A + C), 0.5f * (A - C));
        } else {
            float2 Zk = sw[wid][IDXP(k)];
            float2 Zr = sw[wid][IDXP(256 - k)];
            float Zex = 0.5f * (Zk.x + Zr.x);
            float Zey = 0.5f * (Zk.y - Zr.y);
            float Zox = 0.5f * (Zk.y + Zr.y);
            float Zoy = -0.5f * (Zk.x - Zr.x);
            float2 e = g_pk[k];
            // T = Zo * conj(e)
            float Tx = Zox * e.x + Zoy * e.y;
            float Ty = Zoy * e.x - Zox * e.y;
            float2 A = scaled_norm(Zex + Tx, Zey + Ty, magp[k]);
            float2 C = scaled_norm(Zex - Tx, Zey - Ty, magp[256 - k]);
            float Pex = 0.5f * (A.x + C.x), Pey = 0.5f * (A.y + C.y);
            float Bx  = 0.5f * (A.x - C.x), By  = 0.5f * (A.y - C.y);
            float Qx = Bx * e.x - By * e.y;
            float Qy = Bx * e.y + By * e.x;
            v[j] = make_float2(Pex - Qy, Pey + Qx);
        }
    }
    __syncwarp();   // all sw reads done before istft_tail overwrites sw

    istft_tail(v, sw, ola, wid, l, win,
               ydst + (size_t)b * OUTLEN + (size_t)t0 * HOPSZ);
}

__global__ void k_out(const float* __restrict__ y, float* __restrict__ out) {
    int i = blockIdx.x * blockDim.x + threadIdx.x;
    if (i < BVAL * LTRIM) {
        int b = i / LTRIM;
        int r = i - b * LTRIM;
        int idx = PADN + r;
        out[i] = y[(size_t)b * OUTLEN + idx] * g_invwsq[idx];
    }
}

// ---------------------------------------------------------------------------
extern "C" void kernel_launch(void* const* d_in, const int* in_sizes, int n_in,
                              void* d_out, int out_size) {
    const float* mag = (const float*)d_in[0];   // [32,1024,257]
    const float* ang = (const float*)d_in[1];   // [32,1024,257]
    const float* win = (const float*)d_in[2];   // [512]
    float* out = (float*)d_out;                 // [32,163680]

    float* ya;  cudaGetSymbolAddress((void**)&ya, g_ya4);
    float* yb;  cudaGetSymbolAddress((void**)&yb, g_yb4);

    k_tables<<<1, FBINS>>>();
    k_invwsq<<<(OUTLEN + 255) / 256, 256>>>(win);

    const int zgrid = (BVAL * NSTRIP * STRIP4 + 255) / 256;
    const int fgrid = NFRAMES / FR_PER_BLK;     // 2048 blocks x 512 thr

    k_zero_strips<<<zgrid, 256>>>(ya);
    k_istft_init<<<fgrid, 512>>>(mag, ang, win, ya);   // y_0 in A

    for (int it = 0; it < NITER; it++) {
        float* src = (it & 1) ? yb : ya;
        float* dst = (it & 1) ? ya : yb;
        k_zero_strips<<<zgrid, 256>>>(dst);
        k_gl_step<<<fgrid, 512>>>(mag, win, src, dst);
    }
    // NITER=32 even -> final waveform (istft with phase_32) is in A
    k_out<<<(BVAL * LTRIM + 255) / 256, 256>>>(ya, out);
}

// round 8
// speedup vs baseline: 1.1704x; 1.1704x over previous
#include <cuda_runtime.h>
#include <cstdint>

#define NFFT   512
#define HOPSZ  160
#define PADN   256
#define BVAL   32
#define TVAL   1024
#define FBINS  257
#define LTRIM  163680                  // (TVAL-1)*HOPSZ
#define OUTLEN 164192                  // NFFT + HOPSZ*(TVAL-1)
#define NITER  32
#define TOTF   (BVAL*TVAL*FBINS)       // 8421376
#define NFRAMES (BVAL*TVAL)            // 32768
#define PI_F 3.14159265358979323846f
#define RSQ2 0.70710678118654752440f

#define FR_PER_BLK 16
#define BLK_SPAN   (HOPSZ*(FR_PER_BLK-1) + NFFT)   // 2912
#define BLK_STRIDE (HOPSZ*FR_PER_BLK)              // 2560
#define OVL        (NFFT - HOPSZ)                  // 352 boundary strip
#define SPB        (TVAL / FR_PER_BLK)             // 64 blocks per batch

// ---------------- scratch (device globals; no allocation allowed) ------------
__device__ float4 g_y4[(BVAL * OUTLEN) / 4];       // waveform (normalized), 21 MB
#define G_Y ((float*)g_y4)
__device__ float2 g_ph[TOTF];                      // unit phasor fp32, 67 MB
__device__ float  g_invwsq[OUTLEN];                // NOLA 1/wsq (guarded)
__device__ float2 g_tw[256];                       // e^{+2*pi*i*k/256}
__device__ float2 g_pk[FBINS];                     // (cos(pi k/256), sin(pi k/256))

__device__ __forceinline__ float2 cmulf(float2 a, float2 b) {
    return make_float2(a.x * b.x - a.y * b.y, a.x * b.y + a.y * b.x);
}
__device__ __forceinline__ float2 cadd(float2 a, float2 b) {
    return make_float2(a.x + b.x, a.y + b.y);
}
__device__ __forceinline__ float2 csub(float2 a, float2 b) {
    return make_float2(a.x - b.x, a.y - b.y);
}
template <int SGN>
__device__ __forceinline__ float2 cmuli(float2 a) {   // SGN * i * a
    return (SGN > 0) ? make_float2(-a.y, a.x) : make_float2(a.y, -a.x);
}

// padded smem index: +1 float2 every 16 to break stride-8/16 conflicts
#define IDXP(i) ((i) + ((i) >> 4))
#define SBUF 272

// ---------------------------------------------------------------------------
// 256-pt complex FFT, one warp per transform, 8 complex points per lane.
// Input:  v[j] = x[l + 32*j] (natural order); Output: v[j] = X[j + 8*brev5(l)]
// SGN = -1 forward, +1 inverse (unnormalized)
// ---------------------------------------------------------------------------
template <int SGN>
__device__ __forceinline__ void fft256_warp(float2 v[8], int l) {
    float2 t0 = v[0], t1 = v[4], t2 = v[2], t3 = v[6];
    float2 t4 = v[1], t5 = v[5], t6 = v[3], t7 = v[7];
    float2 a0 = cadd(t0, t1), a1 = csub(t0, t1);
    float2 a2 = cadd(t2, t3), a3 = csub(t2, t3);
    float2 a4 = cadd(t4, t5), a5 = csub(t4, t5);
    float2 a6 = cadd(t6, t7), a7 = csub(t6, t7);
    float2 i3 = cmuli<SGN>(a3), i7 = cmuli<SGN>(a7);
    float2 b0 = cadd(a0, a2), b2 = csub(a0, a2);
    float2 b1 = cadd(a1, i3), b3 = csub(a1, i3);
    float2 b4 = cadd(a4, a6), b6 = csub(a4, a6);
    float2 b5 = cadd(a5, i7), b7 = csub(a5, i7);
    float2 u1 = make_float2(RSQ2 * (b5.x - (float)SGN * b5.y),
                            RSQ2 * (b5.y + (float)SGN * b5.x));
    float2 u2 = cmuli<SGN>(b6);
    float2 u3 = make_float2(-RSQ2 * (b7.x + (float)SGN * b7.y),
                             RSQ2 * ((float)SGN * b7.x - b7.y));
    v[0] = cadd(b0, b4);  v[4] = csub(b0, b4);
    v[1] = cadd(b1, u1);  v[5] = csub(b1, u1);
    v[2] = cadd(b2, u2);  v[6] = csub(b2, u2);
    v[3] = cadd(b3, u3);  v[7] = csub(b3, u3);

    float2 w1 = g_tw[l];
    if (SGN < 0) w1.y = -w1.y;
    float2 w = w1;
    v[1] = cmulf(v[1], w);
#pragma unroll
    for (int k1 = 2; k1 < 8; k1++) {
        w = cmulf(w, w1);
        v[k1] = cmulf(v[k1], w);
    }

#pragma unroll
    for (int s = 0; s < 5; s++) {
        const int m = 16 >> s;
        const bool hi = (l & m) != 0;
        int tidx = (l & (m - 1)) << s;
        float2 tw = g_tw[tidx << 3];
        if (SGN < 0) tw.y = -tw.y;
        if (!hi) tw = make_float2(1.f, 0.f);
        const float p = hi ? -1.f : 1.f;
#pragma unroll
        for (int j = 0; j < 8; j++) {
            float2 o = v[j];
            float2 t;
            t.x = __shfl_xor_sync(0xffffffffu, o.x, m);
            t.y = __shfl_xor_sync(0xffffffffu, o.y, m);
            float2 q = make_float2(t.x + p * o.x, t.y + p * o.y);
            v[j] = cmulf(q, tw);
        }
    }
}

__device__ __forceinline__ int brev5(int l) { return (int)(__brev((unsigned)l) >> 27); }

// ---------------------------------------------------------------------------
__global__ void k_tables() {
    int k = threadIdx.x;
    if (k < 256) {
        float a = (2.0f * PI_F) * (float)k / 256.0f;
        g_tw[k] = make_float2(cosf(a), sinf(a));
    }
    if (k < FBINS) {
        float b = PI_F * (float)k / 256.0f;
        g_pk[k] = make_float2(cosf(b), sinf(b));
    }
}

__global__ void k_invwsq(const float* __restrict__ win) {
    int i = blockIdx.x * blockDim.x + threadIdx.x;
    if (i >= OUTLEN) return;
    int tmax = i / HOPSZ;             if (tmax > TVAL - 1) tmax = TVAL - 1;
    int tmin = (i - (NFFT - 1) + HOPSZ - 1) / HOPSZ;  if (tmin < 0) tmin = 0;
    float s = 0.f;
    for (int t = tmin; t <= tmax; t++) {
        int n = i - t * HOPSZ;
        if (n >= 0 && n < NFFT) { float w = win[n]; s += w * w; }
    }
    g_invwsq[i] = (s > 1e-11f) ? (1.0f / s) : 1.0f;
}

__global__ void k_init_ph(const float* __restrict__ ang) {
    int i = blockIdx.x * blockDim.x + threadIdx.x;
    if (i < TOTF) {
        float s, c;
        sincosf(ang[i], &s, &c);
        g_ph[i] = make_float2(c, s);
    }
}

// OLA boundary strips: 352 floats at q*2560, q = 0..64, per batch
#define NSTRIP (SPB + 1)                        // 65
#define STRIP4 (OVL / 4)                        // 88 float4 per strip
__global__ void k_zero_strips() {
    int i = blockIdx.x * blockDim.x + threadIdx.x;
    const int total = BVAL * NSTRIP * STRIP4;   // 183040
    if (i >= total) return;
    int b = i / (NSTRIP * STRIP4);
    int r = i - b * (NSTRIP * STRIP4);
    int q = r / STRIP4;
    int o = r - q * STRIP4;
    size_t idx = (size_t)b * OUTLEN + (size_t)q * BLK_STRIDE + o * 4;
    *(float4*)(G_Y + idx) = make_float4(0.f, 0.f, 0.f, 0.f);
}

// multiply the boundary strips by invwsq (after istft's raw atomic accumulation)
__global__ void k_norm_strips() {
    int i = blockIdx.x * blockDim.x + threadIdx.x;
    const int total = BVAL * NSTRIP * STRIP4;
    if (i >= total) return;
    int b = i / (NSTRIP * STRIP4);
    int r = i - b * (NSTRIP * STRIP4);
    int q = r / STRIP4;
    int o = r - q * STRIP4;
    int pos = q * BLK_STRIDE + o * 4;
    size_t idx = (size_t)b * OUTLEN + pos;
    float4 v = *(float4*)(G_Y + idx);
    float4 w = *(const float4*)(g_invwsq + pos);
    v.x *= w.x; v.y *= w.y; v.z *= w.z; v.w *= w.w;
    *(float4*)(G_Y + idx) = v;
}

// ---------------------------------------------------------------------------
// ISTFT: spec = mag*phasor -> irfft -> gather-OLA (no smem atomics) ->
// interior normalized plain stores, boundary raw global atomics.
// Block = 16 warps = 16 consecutive frames of one batch.
// ---------------------------------------------------------------------------
__global__ __launch_bounds__(512) void k_istft(const float* __restrict__ mag,
                                               const float* __restrict__ win) {
    __shared__ float2 sw[FR_PER_BLK][SBUF];     // 34.8 KB, irfft frames, natural order
    __shared__ float  swin[NFFT];               // 2 KB, win/256

    const int wid = threadIdx.x >> 5;
    const int l   = threadIdx.x & 31;
    const int s   = blockIdx.x & (SPB - 1);
    const int b   = blockIdx.x >> 6;
    const int t0  = s << 4;
    const int frame = (b << 10) + t0 + wid;
    const float*  magp = mag  + (size_t)frame * FBINS;
    const float2* php  = g_ph + (size_t)frame * FBINS;

    for (int i = threadIdx.x; i < NFFT; i += 512)
        swin[i] = win[i] * (1.0f / 256.0f);

    // Build packed Z[k], k = l + 32j (coalesced gmem reads)
    float2 v[8];
#pragma unroll
    for (int j = 0; j < 8; j++) {
        int k  = l + (j << 5);       // 0..255
        int kr = 256 - k;            // 256..1
        float  mk = magp[k];
        float  mr = magp[kr];
        float2 pk = php[k];
        float2 pr = php[kr];
        float Xkx = mk * pk.x, Xky = mk * pk.y;
        float Xcx = mr * pr.x, Xcy = -mr * pr.y;      // conj(X[256-k])
        if (k == 0) { Xky = 0.f; Xcy = 0.f; }          // irfft ignores imag DC/Nyq
        float Zex = 0.5f * (Xkx + Xcx), Zey = 0.5f * (Xky + Xcy);
        float Bx  = 0.5f * (Xkx - Xcx), By  = 0.5f * (Xky - Xcy);
        float2 e = g_pk[k];                            // e^{+i*pi*k/256}
        float Zox = Bx * e.x - By * e.y;
        float Zoy = Bx * e.y + By * e.x;
        v[j] = make_float2(Zex - Zoy, Zey + Zox);
    }
    fft256_warp<1>(v, l);   // inverse, unnormalized

    // undo bit-reversed lane order -> natural-order frame in sw[wid]
    const int r8 = brev5(l) << 3;
#pragma unroll
    for (int j = 0; j < 8; j++) sw[wid][IDXP(j + r8)] = v[j];
    __syncthreads();

    // gather-OLA: each output sample = sum over <=4 frames, written once
    float* yb = G_Y + (size_t)b * OUTLEN + (size_t)t0 * HOPSZ;
    const int base = t0 * HOPSZ;
    for (int x = threadIdx.x; x < BLK_SPAN; x += 512) {
        int fmin = (x >= 512) ? ((x - 352) / 160) : 0;       // ceil((x-511)/160)
        int fmax = x / 160;  if (fmax > 15) fmax = 15;
        const int odd = x & 1;
        float acc = 0.f;
        for (int f = fmin; f <= fmax; f++) {
            int n = x - f * HOPSZ;                           // 0..511, parity of x
            float2 pr = sw[f][IDXP(n >> 1)];
            float smp = odd ? pr.y : pr.x;
            acc += swin[n] * smp;
        }
        if (x < OVL || x >= BLK_STRIDE) {
            atomicAdd(yb + x, acc);                          // raw; normalized later
        } else {
            yb[x] = acc * g_invwsq[base + x];                // normalized store
        }
    }
}

// ---------------------------------------------------------------------------
// STFT: gather normalized y (fast path: no reflection possible) -> window ->
// rfft(512) -> unit phasor (fp32)
// ---------------------------------------------------------------------------
__device__ __forceinline__ float sample_at(const float* yb, int i) {
    int j = i - PADN;
    j = (j < 0) ? -j : j;
    if (j >= LTRIM) j = 2 * LTRIM - 2 - j;
    return yb[j + PADN];                 // y already normalized
}

__device__ __forceinline__ float2 norm_phasor(float x, float y) {
    float m2 = x * x + y * y;
    if (m2 < 1e-30f) return make_float2(1.f, 0.f);
    float inv = rsqrtf(m2);
    return make_float2(x * inv, y * inv);
}

__global__ __launch_bounds__(256) void k_stft(const float* __restrict__ win) {
    __shared__ float2 sw[8][SBUF];
    const int wid = threadIdx.x >> 5;
    const int l   = threadIdx.x & 31;
    const int frame = (blockIdx.x << 3) + wid;
    const int b = frame >> 10;
    const int t = frame & 1023;
    const float* yb = G_Y + (size_t)b * OUTLEN;
    const int i0 = t * HOPSZ;
    const float2* w2p = (const float2*)win;

    float2 v[8];
    if (t >= 2 && t <= 1021) {
        // no reflection possible: direct aligned float2 loads
        const float2* src = (const float2*)(yb + i0);
#pragma unroll
        for (int j = 0; j < 8; j++) {
            int m = l + (j << 5);
            float2 xy = src[m];
            float2 w  = w2p[m];
            v[j] = make_float2(xy.x * w.x, xy.y * w.y);
        }
    } else {
#pragma unroll
        for (int j = 0; j < 8; j++) {
            int m  = l + (j << 5);
            int n0 = 2 * m;
            float x0 = sample_at(yb, i0 + n0);
            float x1 = sample_at(yb, i0 + n0 + 1);
            float2 w = w2p[m];
            v[j] = make_float2(x0 * w.x, x1 * w.y);
        }
    }
    fft256_warp<-1>(v, l);   // forward

    const int r8 = brev5(l) << 3;
#pragma unroll
    for (int j = 0; j < 8; j++) sw[wid][IDXP(j + r8)] = v[j];
    __syncwarp();

    float2* php = g_ph + (size_t)frame * FBINS;
#pragma unroll
    for (int j = 0; j < 8; j++) {
        int k = l + (j << 5);
        float Xx, Xy;
        if (k == 0) {
            float2 Z0 = sw[wid][IDXP(0)];
            Xx = Z0.x + Z0.y;            // X[0] real
            Xy = 0.f;
        } else {
            float2 Zk = sw[wid][IDXP(k)];
            float2 Zr = sw[wid][IDXP(256 - k)];
            float Zex = 0.5f * (Zk.x + Zr.x);
            float Zey = 0.5f * (Zk.y - Zr.y);
            float Zox = 0.5f * (Zk.y + Zr.y);
            float Zoy = -0.5f * (Zk.x - Zr.x);
            float2 e = g_pk[k];          // W^k = conj(e)
            float Xox = Zox * e.x + Zoy * e.y;
            float Xoy = Zoy * e.x - Zox * e.y;
            Xx = Zex + Xox;
            Xy = Zey + Xoy;
        }
        php[k] = norm_phasor(Xx, Xy);
    }
    if (l == 0) {
        float2 Z0 = sw[wid][IDXP(0)];
        php[256] = norm_phasor(Z0.x - Z0.y, 0.f);   // X[256] real
    }
}

__global__ void k_out(float* __restrict__ out) {
    int i = blockIdx.x * blockDim.x + threadIdx.x;
    if (i < BVAL * LTRIM) {
        int b = i / LTRIM;
        int r = i - b * LTRIM;
        out[i] = G_Y[(size_t)b * OUTLEN + PADN + r];   // already normalized
    }
}

// ---------------------------------------------------------------------------
extern "C" void kernel_launch(void* const* d_in, const int* in_sizes, int n_in,
                              void* d_out, int out_size) {
    const float* mag = (const float*)d_in[0];   // [32,1024,257]
    const float* ang = (const float*)d_in[1];   // [32,1024,257]
    const float* win = (const float*)d_in[2];   // [512]
    float* out = (float*)d_out;                 // [32,163680]

    k_tables<<<1, FBINS>>>();
    k_invwsq<<<(OUTLEN + 255) / 256, 256>>>(win);
    k_init_ph<<<TOTF / 256, 256>>>(ang);

    const int zgrid = (BVAL * NSTRIP * STRIP4 + 255) / 256;
    const int igrid = NFRAMES / FR_PER_BLK;     // 2048 blocks x 512 thr
    const int sgrid = NFRAMES / 8;              // 4096 blocks x 256 thr

    for (int it = 0; it < NITER; it++) {
        k_zero_strips<<<zgrid, 256>>>();
        k_istft<<<igrid, 512>>>(mag, win);
        k_norm_strips<<<zgrid, 256>>>();
        k_stft<<<sgrid, 256>>>(win);
    }
    k_zero_strips<<<zgrid, 256>>>();
    k_istft<<<igrid, 512>>>(mag, win);
    k_norm_strips<<<zgrid, 256>>>();
    k_out<<<(BVAL * LTRIM + 255) / 256, 256>>>(out);
}

// round 10
// speedup vs baseline: 1.2316x; 1.0523x over previous
#include <cuda_runtime.h>
#include <cstdint>

#define NFFT   512
#define HOPSZ  160
#define PADN   256
#define BVAL   32
#define TVAL   1024
#define FBINS  257
#define LTRIM  163680                  // (TVAL-1)*HOPSZ
#define OUTLEN 164192                  // NFFT + HOPSZ*(TVAL-1)
#define NITER  32
#define TOTF   (BVAL*TVAL*FBINS)       // 8421376
#define NFRAMES (BVAL*TVAL)            // 32768
#define PI_F 3.14159265358979323846f
#define RSQ2 0.70710678118654752440f

#define FR_PER_BLK 16
#define BLK_SPAN   (HOPSZ*(FR_PER_BLK-1) + NFFT)   // 2912
#define BLK_STRIDE (HOPSZ*FR_PER_BLK)              // 2560
#define OVL        (NFFT - HOPSZ)                  // 352 boundary strip
#define SPB        (TVAL / FR_PER_BLK)             // 64 blocks per batch

// ---------------- scratch (device globals; no allocation allowed) ------------
__device__ float4 g_y4[(BVAL * OUTLEN) / 4];       // waveform (normalized), 21 MB
#define G_Y ((float*)g_y4)
__device__ float2 g_ph[TOTF];                      // unit phasor fp32, 67 MB
__device__ float  g_invwsq[OUTLEN];                // NOLA 1/wsq (guarded)
__device__ float2 g_tw[256];                       // e^{+2*pi*i*k/256}
__device__ float2 g_pk[FBINS];                     // (cos(pi k/256), sin(pi k/256))

__device__ __forceinline__ float2 cmulf(float2 a, float2 b) {
    return make_float2(a.x * b.x - a.y * b.y, a.x * b.y + a.y * b.x);
}
__device__ __forceinline__ float2 cadd(float2 a, float2 b) {
    return make_float2(a.x + b.x, a.y + b.y);
}
__device__ __forceinline__ float2 csub(float2 a, float2 b) {
    return make_float2(a.x - b.x, a.y - b.y);
}
template <int SGN>
__device__ __forceinline__ float2 cmuli(float2 a) {   // SGN * i * a
    return (SGN > 0) ? make_float2(-a.y, a.x) : make_float2(a.y, -a.x);
}

// padded smem index: +1 float2 every 16 to break stride-8/16 conflicts
#define IDXP(i) ((i) + ((i) >> 4))
#define SBUF 272

// ---------------------------------------------------------------------------
// 256-pt complex FFT, one warp per transform, 8 complex points per lane.
// Input:  v[j] = x[l + 32*j] (natural order); Output: v[j] = X[j + 8*brev5(l)]
// SGN = -1 forward, +1 inverse (unnormalized)
// ---------------------------------------------------------------------------
template <int SGN>
__device__ __forceinline__ void fft256_warp(float2 v[8], int l) {
    float2 t0 = v[0], t1 = v[4], t2 = v[2], t3 = v[6];
    float2 t4 = v[1], t5 = v[5], t6 = v[3], t7 = v[7];
    float2 a0 = cadd(t0, t1), a1 = csub(t0, t1);
    float2 a2 = cadd(t2, t3), a3 = csub(t2, t3);
    float2 a4 = cadd(t4, t5), a5 = csub(t4, t5);
    float2 a6 = cadd(t6, t7), a7 = csub(t6, t7);
    float2 i3 = cmuli<SGN>(a3), i7 = cmuli<SGN>(a7);
    float2 b0 = cadd(a0, a2), b2 = csub(a0, a2);
    float2 b1 = cadd(a1, i3), b3 = csub(a1, i3);
    float2 b4 = cadd(a4, a6), b6 = csub(a4, a6);
    float2 b5 = cadd(a5, i7), b7 = csub(a5, i7);
    float2 u1 = make_float2(RSQ2 * (b5.x - (float)SGN * b5.y),
                            RSQ2 * (b5.y + (float)SGN * b5.x));
    float2 u2 = cmuli<SGN>(b6);
    float2 u3 = make_float2(-RSQ2 * (b7.x + (float)SGN * b7.y),
                             RSQ2 * ((float)SGN * b7.x - b7.y));
    v[0] = cadd(b0, b4);  v[4] = csub(b0, b4);
    v[1] = cadd(b1, u1);  v[5] = csub(b1, u1);
    v[2] = cadd(b2, u2);  v[6] = csub(b2, u2);
    v[3] = cadd(b3, u3);  v[7] = csub(b3, u3);

    float2 w1 = g_tw[l];
    if (SGN < 0) w1.y = -w1.y;
    float2 w = w1;
    v[1] = cmulf(v[1], w);
#pragma unroll
    for (int k1 = 2; k1 < 8; k1++) {
        w = cmulf(w, w1);
        v[k1] = cmulf(v[k1], w);
    }

#pragma unroll
    for (int s = 0; s < 5; s++) {
        const int m = 16 >> s;
        const bool hi = (l & m) != 0;
        int tidx = (l & (m - 1)) << s;
        float2 tw = g_tw[tidx << 3];
        if (SGN < 0) tw.y = -tw.y;
        if (!hi) tw = make_float2(1.f, 0.f);
        const float p = hi ? -1.f : 1.f;
#pragma unroll
        for (int j = 0; j < 8; j++) {
            float2 o = v[j];
            float2 t;
            t.x = __shfl_xor_sync(0xffffffffu, o.x, m);
            t.y = __shfl_xor_sync(0xffffffffu, o.y, m);
            float2 q = make_float2(t.x + p * o.x, t.y + p * o.y);
            v[j] = cmulf(q, tw);
        }
    }
}

__device__ __forceinline__ int brev5(int l) { return (int)(__brev((unsigned)l) >> 27); }

// ---------------------------------------------------------------------------
__global__ void k_tables() {
    int k = threadIdx.x;
    if (k < 256) {
        float a = (2.0f * PI_F) * (float)k / 256.0f;
        g_tw[k] = make_float2(cosf(a), sinf(a));
    }
    if (k < FBINS) {
        float b = PI_F * (float)k / 256.0f;
        g_pk[k] = make_float2(cosf(b), sinf(b));
    }
}

__global__ void k_invwsq(const float* __restrict__ win) {
    int i = blockIdx.x * blockDim.x + threadIdx.x;
    if (i >= OUTLEN) return;
    int tmax = i / HOPSZ;             if (tmax > TVAL - 1) tmax = TVAL - 1;
    int tmin = (i - (NFFT - 1) + HOPSZ - 1) / HOPSZ;  if (tmin < 0) tmin = 0;
    float s = 0.f;
    for (int t = tmin; t <= tmax; t++) {
        int n = i - t * HOPSZ;
        if (n >= 0 && n < NFFT) { float w = win[n]; s += w * w; }
    }
    g_invwsq[i] = (s > 1e-11f) ? (1.0f / s) : 1.0f;
}

__global__ void k_init_ph(const float* __restrict__ ang) {
    int i = blockIdx.x * blockDim.x + threadIdx.x;
    if (i < TOTF) {
        float s, c;
        sincosf(ang[i], &s, &c);
        g_ph[i] = make_float2(c, s);
    }
}

// OLA boundary strips: 352 floats at q*2560, q = 0..64, per batch
#define NSTRIP (SPB + 1)                        // 65
#define STRIP4 (OVL / 4)                        // 88 float4 per strip
__global__ void k_zero_strips() {
    int i = blockIdx.x * blockDim.x + threadIdx.x;
    const int total = BVAL * NSTRIP * STRIP4;   // 183040
    if (i >= total) return;
    int b = i / (NSTRIP * STRIP4);
    int r = i - b * (NSTRIP * STRIP4);
    int q = r / STRIP4;
    int o = r - q * STRIP4;
    size_t idx = (size_t)b * OUTLEN + (size_t)q * BLK_STRIDE + o * 4;
    *(float4*)(G_Y + idx) = make_float4(0.f, 0.f, 0.f, 0.f);
}

// multiply boundary strips by invwsq (after istft's raw atomic accumulation)
__global__ void k_norm_strips() {
    int i = blockIdx.x * blockDim.x + threadIdx.x;
    const int total = BVAL * NSTRIP * STRIP4;
    if (i >= total) return;
    int b = i / (NSTRIP * STRIP4);
    int r = i - b * (NSTRIP * STRIP4);
    int q = r / STRIP4;
    int o = r - q * STRIP4;
    int pos = q * BLK_STRIDE + o * 4;
    size_t idx = (size_t)b * OUTLEN + pos;
    float4 v = *(float4*)(G_Y + idx);
    float4 w = *(const float4*)(g_invwsq + pos);
    v.x *= w.x; v.y *= w.y; v.z *= w.z; v.w *= w.w;
    *(float4*)(G_Y + idx) = v;
}

// ---------------------------------------------------------------------------
// ISTFT: spec = mag*phasor -> irfft -> smem-atomic block OLA ->
// interior normalized plain stores, boundary raw global atomics.
// Block = 16 warps = 16 consecutive frames of one batch.
// ---------------------------------------------------------------------------
__global__ __launch_bounds__(512) void k_istft(const float* __restrict__ mag,
                                               const float* __restrict__ win) {
    __shared__ float2 sw[FR_PER_BLK][SBUF];     // 34.8 KB
    __shared__ float4 ola4[BLK_SPAN / 4];       // 11.6 KB
    float* ola = (float*)ola4;

    const int wid = threadIdx.x >> 5;
    const int l   = threadIdx.x & 31;
    const int s   = blockIdx.x & (SPB - 1);
    const int b   = blockIdx.x >> 6;
    const int t0  = s << 4;
    const int frame = (b << 10) + t0 + wid;
    const float*  magp = mag  + (size_t)frame * FBINS;
    const float2* php  = g_ph + (size_t)frame * FBINS;

    for (int i = threadIdx.x; i < BLK_SPAN; i += 512) ola[i] = 0.f;
    __syncthreads();

    // Build packed Z[k], k = l + 32j (coalesced gmem reads), fp32 phasor
    float2 v[8];
#pragma unroll
    for (int j = 0; j < 8; j++) {
        int k  = l + (j << 5);       // 0..255
        int kr = 256 - k;            // 256..1
        float  mk = magp[k];
        float  mr = magp[kr];
        float2 pk = php[k];
        float2 pr = php[kr];
        float Xkx = mk * pk.x, Xky = mk * pk.y;
        float Xcx = mr * pr.x, Xcy = -mr * pr.y;      // conj(X[256-k])
        if (k == 0) { Xky = 0.f; Xcy = 0.f; }          // irfft ignores imag DC/Nyq
        float Zex = 0.5f * (Xkx + Xcx), Zey = 0.5f * (Xky + Xcy);
        float Bx  = 0.5f * (Xkx - Xcx), By  = 0.5f * (Xky - Xcy);
        float2 e = g_pk[k];                            // e^{+i*pi*k/256}
        float Zox = Bx * e.x - By * e.y;
        float Zoy = Bx * e.y + By * e.x;
        v[j] = make_float2(Zex - Zoy, Zey + Zox);
    }
    fft256_warp<1>(v, l);   // inverse, unnormalized

    // undo bit-reversed lane order via warp-private smem
    const int r8 = brev5(l) << 3;
#pragma unroll
    for (int j = 0; j < 8; j++) sw[wid][IDXP(j + r8)] = v[j];
    __syncwarp();

    // windowed accumulate into block OLA (smem atomics, 2-way conflicts)
    float* olap = ola + wid * HOPSZ;
    const float2* w2p = (const float2*)win;
#pragma unroll
    for (int j = 0; j < 8; j++) {
        int m = l + (j << 5);
        float2 z = sw[wid][IDXP(m)];
        float2 w = w2p[m];
        atomicAdd(olap + 2 * m,     z.x * (1.0f / 256.0f) * w.x);
        atomicAdd(olap + 2 * m + 1, z.y * (1.0f / 256.0f) * w.y);
    }
    __syncthreads();

    // write out: interior normalized float stores, boundaries raw global atomics
    float* yb = G_Y + (size_t)b * OUTLEN + (size_t)t0 * HOPSZ;
    const int base = t0 * HOPSZ;
    for (int i = threadIdx.x; i < BLK_STRIDE - OVL; i += 512) {   // 2208 interior
        int x = OVL + i;
        yb[x] = ola[x] * g_invwsq[base + x];
    }
    for (int i = threadIdx.x; i < 2 * OVL; i += 512) {            // 704 boundary
        int x = (i < OVL) ? i : (BLK_STRIDE - OVL + i);
        atomicAdd(yb + x, ola[x]);
    }
}

// ---------------------------------------------------------------------------
// STFT: gather normalized y (fast path for interior frames) -> window ->
// rfft(512) -> unit phasor (fp32)
// ---------------------------------------------------------------------------
__device__ __forceinline__ float sample_at(const float* yb, int i) {
    int j = i - PADN;
    j = (j < 0) ? -j : j;
    if (j >= LTRIM) j = 2 * LTRIM - 2 - j;
    return yb[j + PADN];                 // y already normalized
}

__device__ __forceinline__ float2 norm_phasor(float x, float y) {
    float m2 = x * x + y * y;
    if (m2 < 1e-30f) return make_float2(1.f, 0.f);
    float inv = rsqrtf(m2);
    return make_float2(x * inv, y * inv);
}

__global__ __launch_bounds__(256) void k_stft(const float* __restrict__ win) {
    __shared__ float2 sw[8][SBUF];
    const int wid = threadIdx.x >> 5;
    const int l   = threadIdx.x & 31;
    const int frame = (blockIdx.x << 3) + wid;
    const int b = frame >> 10;
    const int t = frame & 1023;
    const float* yb = G_Y + (size_t)b * OUTLEN;
    const int i0 = t * HOPSZ;
    const float2* w2p = (const float2*)win;

    float2 v[8];
    if (t >= 2 && t <= 1021) {
        const float2* src = (const float2*)(yb + i0);
#pragma unroll
        for (int j = 0; j < 8; j++) {
            int m = l + (j << 5);
            float2 xy = src[m];
            float2 w  = w2p[m];
            v[j] = make_float2(xy.x * w.x, xy.y * w.y);
        }
    } else {
#pragma unroll
        for (int j = 0; j < 8; j++) {
            int m  = l + (j << 5);
            int n0 = 2 * m;
            float x0 = sample_at(yb, i0 + n0);
            float x1 = sample_at(yb, i0 + n0 + 1);
            float2 w = w2p[m];
            v[j] = make_float2(x0 * w.x, x1 * w.y);
        }
    }
    fft256_warp<-1>(v, l);   // forward

    const int r8 = brev5(l) << 3;
#pragma unroll
    for (int j = 0; j < 8; j++) sw[wid][IDXP(j + r8)] = v[j];
    __syncwarp();

    float2* php = g_ph + (size_t)frame * FBINS;
#pragma unroll
    for (int j = 0; j < 8; j++) {
        int k = l + (j << 5);
        float Xx, Xy;
        if (k == 0) {
            float2 Z0 = sw[wid][IDXP(0)];
            Xx = Z0.x + Z0.y;            // X[0] real
            Xy = 0.f;
        } else {
            float2 Zk = sw[wid][IDXP(k)];
            float2 Zr = sw[wid][IDXP(256 - k)];
            float Zex = 0.5f * (Zk.x + Zr.x);
            float Zey = 0.5f * (Zk.y - Zr.y);
            float Zox = 0.5f * (Zk.y + Zr.y);
            float Zoy = -0.5f * (Zk.x - Zr.x);
            float2 e = g_pk[k];          // W^k = conj(e)
            float Xox = Zox * e.x + Zoy * e.y;
            float Xoy = Zoy * e.x - Zox * e.y;
            Xx = Zex + Xox;
            Xy = Zey + Xoy;
        }
        php[k] = norm_phasor(Xx, Xy);
    }
    if (l == 0) {
        float2 Z0 = sw[wid][IDXP(0)];
        php[256] = norm_phasor(Z0.x - Z0.y, 0.f);   // X[256] real
    }
}

__global__ void k_out(float* __restrict__ out) {
    int i = blockIdx.x * blockDim.x + threadIdx.x;
    if (i < BVAL * LTRIM) {
        int b = i / LTRIM;
        int r = i - b * LTRIM;
        out[i] = G_Y[(size_t)b * OUTLEN + PADN + r];   // already normalized
    }
}

// ---------------------------------------------------------------------------
extern "C" void kernel_launch(void* const* d_in, const int* in_sizes, int n_in,
                              void* d_out, int out_size) {
    const float* mag = (const float*)d_in[0];   // [32,1024,257]
    const float* ang = (const float*)d_in[1];   // [32,1024,257]
    const float* win = (const float*)d_in[2];   // [512]
    float* out = (float*)d_out;                 // [32,163680]

    k_tables<<<1, FBINS>>>();
    k_invwsq<<<(OUTLEN + 255) / 256, 256>>>(win);
    k_init_ph<<<TOTF / 256, 256>>>(ang);

    const int zgrid = (BVAL * NSTRIP * STRIP4 + 255) / 256;
    const int igrid = NFRAMES / FR_PER_BLK;     // 2048 blocks x 512 thr
    const int sgrid = NFRAMES / 8;              // 4096 blocks x 256 thr

    for (int it = 0; it < NITER; it++) {
        k_zero_strips<<<zgrid, 256>>>();
        k_istft<<<igrid, 512>>>(mag, win);
        k_norm_strips<<<zgrid, 256>>>();
        k_stft<<<sgrid, 256>>>(win);
    }
    k_zero_strips<<<zgrid, 256>>>();
    k_istft<<<igrid, 512>>>(mag, win);
    k_norm_strips<<<zgrid, 256>>>();
    k_out<<<(BVAL * LTRIM + 255) / 256, 256>>>(out);
}

// round 11
// speedup vs baseline: 1.4565x; 1.1827x over previous
#include <cuda_runtime.h>
#include <cstdint>

#define NFFT   512
#define HOPSZ  160
#define PADN   256
#define BVAL   32
#define TVAL   1024
#define FBINS  257
#define LTRIM  163680                  // (TVAL-1)*HOPSZ
#define OUTLEN 164192                  // NFFT + HOPSZ*(TVAL-1)
#define NITER  32
#define TOTF   (BVAL*TVAL*FBINS)       // 8421376
#define NFRAMES (BVAL*TVAL)            // 32768
#define PI_F 3.14159265358979323846f
#define RSQ2 0.70710678118654752440f

// ---------------- scratch (device globals; no allocation allowed) ------------
__device__ float4 g_y4[(BVAL * OUTLEN) / 4];           // OLA buffer (raw), 21 MB
#define G_Y ((float*)g_y4)
__device__ float2 g_ph[TOTF];                          // unit phasor fp32, 67 MB
__device__ float  g_invwsq[OUTLEN];                    // NOLA 1/wsq (guarded)
__device__ float2 g_tw[256];                           // e^{+2*pi*i*k/256}
__device__ float2 g_pk[FBINS];                         // (cos(pi k/256), sin(pi k/256))

__device__ __forceinline__ float2 cmulf(float2 a, float2 b) {
    return make_float2(a.x * b.x - a.y * b.y, a.x * b.y + a.y * b.x);
}
__device__ __forceinline__ float2 cadd(float2 a, float2 b) {
    return make_float2(a.x + b.x, a.y + b.y);
}
__device__ __forceinline__ float2 csub(float2 a, float2 b) {
    return make_float2(a.x - b.x, a.y - b.y);
}
template <int SGN>
__device__ __forceinline__ float2 cmuli(float2 a) {   // SGN * i * a
    return (SGN > 0) ? make_float2(-a.y, a.x) : make_float2(a.y, -a.x);
}

// padded smem index: +1 float2 every 16 to break stride-8/16 conflicts
#define IDXP(i) ((i) + ((i) >> 4))
#define SBUF 272

// ---------------------------------------------------------------------------
// 256-pt complex FFT, one warp per transform, 8 complex points per lane.
// Input:  v[j] = x[l + 32*j] (natural order); Output: v[j] = X[j + 8*brev5(l)]
// SGN = -1 forward, +1 inverse (unnormalized).
// Cross-lane 32-pt FFT uses fused radix-4/radix-4/radix-2 (deferred twiddles):
// identical dataflow to 5 radix-2 DIF stages, but only 2 cmul rounds.
// ---------------------------------------------------------------------------
template <int SGN>
__device__ __forceinline__ void fft256_warp(float2 v[8], int l) {
    // ---- radix-8 over j (stride-32 dim), registers ----
    float2 t0 = v[0], t1 = v[4], t2 = v[2], t3 = v[6];
    float2 t4 = v[1], t5 = v[5], t6 = v[3], t7 = v[7];
    float2 a0 = cadd(t0, t1), a1 = csub(t0, t1);
    float2 a2 = cadd(t2, t3), a3 = csub(t2, t3);
    float2 a4 = cadd(t4, t5), a5 = csub(t4, t5);
    float2 a6 = cadd(t6, t7), a7 = csub(t6, t7);
    float2 i3 = cmuli<SGN>(a3), i7 = cmuli<SGN>(a7);
    float2 b0 = cadd(a0, a2), b2 = csub(a0, a2);
    float2 b1 = cadd(a1, i3), b3 = csub(a1, i3);
    float2 b4 = cadd(a4, a6), b6 = csub(a4, a6);
    float2 b5 = cadd(a5, i7), b7 = csub(a5, i7);
    float2 u1 = make_float2(RSQ2 * (b5.x - (float)SGN * b5.y),
                            RSQ2 * (b5.y + (float)SGN * b5.x));
    float2 u2 = cmuli<SGN>(b6);
    float2 u3 = make_float2(-RSQ2 * (b7.x + (float)SGN * b7.y),
                             RSQ2 * ((float)SGN * b7.x - b7.y));
    v[0] = cadd(b0, b4);  v[4] = csub(b0, b4);
    v[1] = cadd(b1, u1);  v[5] = csub(b1, u1);
    v[2] = cadd(b2, u2);  v[6] = csub(b2, u2);
    v[3] = cadd(b3, u3);  v[7] = csub(b3, u3);

    // ---- twiddle e^{SGN*2*pi*i*l*k1/256} via power chain ----
    float2 w1 = g_tw[l];
    if (SGN < 0) w1.y = -w1.y;
    float2 w = w1;
    v[1] = cmulf(v[1], w);
#pragma unroll
    for (int k1 = 2; k1 < 8; k1++) {
        w = cmulf(w, w1);
        v[k1] = cmulf(v[k1], w);
    }

    // ---- cross-lane 32-pt FFT: 5 xor-shfl rounds, 2 cmul rounds ----
    const int lb4 = (l >> 4) & 1, lb3 = (l >> 3) & 1;
    const int lb2 = (l >> 2) & 1, lb1 = (l >> 1) & 1, lb0 = l & 1;

    // Round 1: xor 16, sign by b4; lanes (b4&b3) pick up W32^8 = SGN*i
    {
        const float p = lb4 ? -1.f : 1.f;
        const bool rot = (lb4 & lb3) != 0;
#pragma unroll
        for (int j = 0; j < 8; j++) {
            float2 o = v[j];
            float tx = __shfl_xor_sync(0xffffffffu, o.x, 16);
            float ty = __shfl_xor_sync(0xffffffffu, o.y, 16);
            float2 q = make_float2(tx + p * o.x, ty + p * o.y);
            v[j] = rot ? cmuli<SGN>(q) : q;
        }
    }
    // Round 2: xor 8, sign by b3; combined twiddle W32^{(l&7)*e1}, e1 = b4+2*b3
    {
        const float p = lb3 ? -1.f : 1.f;
        const int e1 = lb4 + 2 * lb3;
        float2 tw = g_tw[((l & 7) * e1) << 3];
        if (SGN < 0) tw.y = -tw.y;
#pragma unroll
        for (int j = 0; j < 8; j++) {
            float2 o = v[j];
            float tx = __shfl_xor_sync(0xffffffffu, o.x, 8);
            float ty = __shfl_xor_sync(0xffffffffu, o.y, 8);
            float2 q = make_float2(tx + p * o.x, ty + p * o.y);
            v[j] = cmulf(q, tw);
        }
    }
    // Round 3: xor 4, sign by b2; lanes (b2&b1) pick up W8^2 = SGN*i
    {
        const float p = lb2 ? -1.f : 1.f;
        const bool rot = (lb2 & lb1) != 0;
#pragma unroll
        for (int j = 0; j < 8; j++) {
            float2 o = v[j];
            float tx = __shfl_xor_sync(0xffffffffu, o.x, 4);
            float ty = __shfl_xor_sync(0xffffffffu, o.y, 4);
            float2 q = make_float2(tx + p * o.x, ty + p * o.y);
            v[j] = rot ? cmuli<SGN>(q) : q;
        }
    }
    // Round 4: xor 2, sign by b1; combined twiddle W8^{b0*e2}, e2 = b2+2*b1
    {
        const float p = lb1 ? -1.f : 1.f;
        const int e2 = lb2 + 2 * lb1;
        float2 tw = g_tw[(lb0 * e2) << 5];
        if (SGN < 0) tw.y = -tw.y;
#pragma unroll
        for (int j = 0; j < 8; j++) {
            float2 o = v[j];
            float tx = __shfl_xor_sync(0xffffffffu, o.x, 2);
            float ty = __shfl_xor_sync(0xffffffffu, o.y, 2);
            float2 q = make_float2(tx + p * o.x, ty + p * o.y);
            v[j] = cmulf(q, tw);
        }
    }
    // Round 5: xor 1, sign by b0, no twiddle (W^0)
    {
        const float p = lb0 ? -1.f : 1.f;
#pragma unroll
        for (int j = 0; j < 8; j++) {
            float2 o = v[j];
            float tx = __shfl_xor_sync(0xffffffffu, o.x, 1);
            float ty = __shfl_xor_sync(0xffffffffu, o.y, 1);
            v[j] = make_float2(tx + p * o.x, ty + p * o.y);
        }
    }
}

__device__ __forceinline__ int brev5(int l) { return (int)(__brev((unsigned)l) >> 27); }

// ---------------------------------------------------------------------------
__global__ void k_tables() {
    int k = threadIdx.x;
    if (k < 256) {
        float a = (2.0f * PI_F) * (float)k / 256.0f;
        g_tw[k] = make_float2(cosf(a), sinf(a));
    }
    if (k < FBINS) {
        float b = PI_F * (float)k / 256.0f;
        g_pk[k] = make_float2(cosf(b), sinf(b));
    }
}

__global__ void k_invwsq(const float* __restrict__ win) {
    int i = blockIdx.x * blockDim.x + threadIdx.x;
    if (i >= OUTLEN) return;
    int tmax = i / HOPSZ;             if (tmax > TVAL - 1) tmax = TVAL - 1;
    int tmin = (i - (NFFT - 1) + HOPSZ - 1) / HOPSZ;  if (tmin < 0) tmin = 0;
    float s = 0.f;
    for (int t = tmin; t <= tmax; t++) {
        int n = i - t * HOPSZ;
        if (n >= 0 && n < NFFT) { float w = win[n]; s += w * w; }
    }
    g_invwsq[i] = (s > 1e-11f) ? (1.0f / s) : 1.0f;
}

__global__ void k_init_ph(const float* __restrict__ ang) {
    int i = blockIdx.x * blockDim.x + threadIdx.x;
    if (i < TOTF) {
        float s, c;
        sincosf(ang[i], &s, &c);
        g_ph[i] = make_float2(c, s);
    }
}

__global__ void k_zero_y() {
    int i = blockIdx.x * blockDim.x + threadIdx.x;
    if (i < (BVAL * OUTLEN) / 4) g_y4[i] = make_float4(0.f, 0.f, 0.f, 0.f);
}

// ---------------------------------------------------------------------------
// ISTFT: spec = mag * phasor -> irfft(512) -> * window -> atomic OLA into g_y
// one frame per warp, 8 warps per block (R3-proven structure)
// ---------------------------------------------------------------------------
__global__ __launch_bounds__(256) void k_istft(const float* __restrict__ mag,
                                               const float* __restrict__ win) {
    __shared__ float2 sw[8][SBUF];
    const int wid = threadIdx.x >> 5;
    const int l   = threadIdx.x & 31;
    const int frame = (blockIdx.x << 3) + wid;
    const int b = frame >> 10;
    const int t = frame & 1023;
    const float*  magp = mag  + (size_t)frame * FBINS;
    const float2* php  = g_ph + (size_t)frame * FBINS;

    float2 v[8];
#pragma unroll
    for (int j = 0; j < 8; j++) {
        int k  = l + (j << 5);       // 0..255
        int kr = 256 - k;            // 256..1
        float  mk = magp[k];
        float  mr = magp[kr];
        float2 pk = php[k];
        float2 pr = php[kr];
        float Xkx = mk * pk.x, Xky = mk * pk.y;
        float Xcx = mr * pr.x, Xcy = -mr * pr.y;   // conj(X[256-k])
        if (k == 0) { Xky = 0.f; Xcy = 0.f; }      // irfft ignores imag DC/Nyq
        float Zex = 0.5f * (Xkx + Xcx), Zey = 0.5f * (Xky + Xcy);
        float Bx  = 0.5f * (Xkx - Xcx), By  = 0.5f * (Xky - Xcy);
        float2 e = g_pk[k];                        // e^{+i*pi*k/256}
        float Zox = Bx * e.x - By * e.y;
        float Zoy = Bx * e.y + By * e.x;
        v[j] = make_float2(Zex - Zoy, Zey + Zox);
    }
    fft256_warp<1>(v, l);   // inverse, unnormalized

    const int r8 = brev5(l) << 3;
#pragma unroll
    for (int j = 0; j < 8; j++) sw[wid][IDXP(j + r8)] = v[j];
    __syncwarp();

    float* yb = G_Y + (size_t)b * OUTLEN + t * HOPSZ;
    const float2* w2p = (const float2*)win;
#pragma unroll
    for (int j = 0; j < 8; j++) {
        int m = l + (j << 5);
        float2 z = sw[wid][IDXP(m)];
        float2 w = w2p[m];
        atomicAdd(yb + 2 * m,     z.x * (1.0f / 256.0f) * w.x);
        atomicAdd(yb + 2 * m + 1, z.y * (1.0f / 256.0f) * w.y);
    }
}

// ---------------------------------------------------------------------------
// STFT: gather (reflect-pad + NOLA) -> window -> rfft(512) -> unit phasor
// interior frames (no reflection possible): vectorized float2 fast path
// ---------------------------------------------------------------------------
__device__ __forceinline__ float sample_at(const float* yb, int i) {
    int j = i - PADN;
    j = (j < 0) ? -j : j;
    if (j >= LTRIM) j = 2 * LTRIM - 2 - j;
    int idx = j + PADN;
    return yb[idx] * g_invwsq[idx];
}

__device__ __forceinline__ float2 norm_phasor(float x, float y) {
    float m2 = x * x + y * y;
    if (m2 < 1e-30f) return make_float2(1.f, 0.f);
    float inv = rsqrtf(m2);
    return make_float2(x * inv, y * inv);
}

__global__ __launch_bounds__(256) void k_stft(const float* __restrict__ win) {
    __shared__ float2 sw[8][SBUF];
    const int wid = threadIdx.x >> 5;
    const int l   = threadIdx.x & 31;
    const int frame = (blockIdx.x << 3) + wid;
    const int b = frame >> 10;
    const int t = frame & 1023;
    const float* yb = G_Y + (size_t)b * OUTLEN;
    const int i0 = t * HOPSZ;
    const float2* w2p = (const float2*)win;

    float2 v[8];
    if (t >= 2 && t <= 1021) {
        const float2* ysrc = (const float2*)(yb + i0);
        const float2* iwp  = (const float2*)(g_invwsq + i0);
#pragma unroll
        for (int j = 0; j < 8; j++) {
            int m = l + (j << 5);
            float2 xy = ysrc[m];
            float2 iw = iwp[m];
            float2 w  = w2p[m];
            v[j] = make_float2(xy.x * iw.x * w.x, xy.y * iw.y * w.y);
        }
    } else {
#pragma unroll
        for (int j = 0; j < 8; j++) {
            int m  = l + (j << 5);
            int n0 = 2 * m;
            float x0 = sample_at(yb, i0 + n0);
            float x1 = sample_at(yb, i0 + n0 + 1);
            float2 w = w2p[m];
            v[j] = make_float2(x0 * w.x, x1 * w.y);
        }
    }
    fft256_warp<-1>(v, l);   // forward

    const int r8 = brev5(l) << 3;
#pragma unroll
    for (int j = 0; j < 8; j++) sw[wid][IDXP(j + r8)] = v[j];
    __syncwarp();

    float2* php = g_ph + (size_t)frame * FBINS;
#pragma unroll
    for (int j = 0; j < 8; j++) {
        int k = l + (j << 5);
        float Xx, Xy;
        if (k == 0) {
            float2 Z0 = sw[wid][IDXP(0)];
            Xx = Z0.x + Z0.y;            // X[0] real
            Xy = 0.f;
        } else {
            float2 Zk = sw[wid][IDXP(k)];
            float2 Zr = sw[wid][IDXP(256 - k)];
            float Zex = 0.5f * (Zk.x + Zr.x);
            float Zey = 0.5f * (Zk.y - Zr.y);
            float Zox = 0.5f * (Zk.y + Zr.y);
            float Zoy = -0.5f * (Zk.x - Zr.x);
            float2 e = g_pk[k];          // W^k = conj(e)
            float Xox = Zox * e.x + Zoy * e.y;
            float Xoy = Zoy * e.x - Zox * e.y;
            Xx = Zex + Xox;
            Xy = Zey + Xoy;
        }
        php[k] = norm_phasor(Xx, Xy);
    }
    if (l == 0) {
        float2 Z0 = sw[wid][IDXP(0)];
        php[256] = norm_phasor(Z0.x - Z0.y, 0.f);   // X[256] real
    }
}

__global__ void k_out(float* __restrict__ out) {
    int i = blockIdx.x * blockDim.x + threadIdx.x;
    if (i < BVAL * LTRIM) {
        int b = i / LTRIM;
        int r = i - b * LTRIM;
        int idx = PADN + r;
        out[i] = G_Y[(size_t)b * OUTLEN + idx] * g_invwsq[idx];
    }
}

// ---------------------------------------------------------------------------
extern "C" void kernel_launch(void* const* d_in, const int* in_sizes, int n_in,
                              void* d_out, int out_size) {
    const float* mag = (const float*)d_in[0];   // [32,1024,257]
    const float* ang = (const float*)d_in[1];   // [32,1024,257]
    const float* win = (const float*)d_in[2];   // [512]
    float* out = (float*)d_out;                 // [32,163680]

    k_tables<<<1, FBINS>>>();
    k_invwsq<<<(OUTLEN + 255) / 256, 256>>>(win);
    k_init_ph<<<TOTF / 256, 256>>>(ang);

    const int zgrid = ((BVAL * OUTLEN) / 4 + 255) / 256;
    const int fgrid = NFRAMES / 8;   // 8 frames (warps) per block
    for (int it = 0; it < NITER; it++) {
        k_zero_y<<<zgrid, 256>>>();
        k_istft<<<fgrid, 256>>>(mag, win);
        k_stft<<<fgrid, 256>>>(win);
    }
    k_zero_y<<<zgrid, 256>>>();
    k_istft<<<fgrid, 256>>>(mag, win);
    k_out<<<(BVAL * LTRIM + 255) / 256, 256>>>(out);
}

// round 12
// speedup vs baseline: 1.8382x; 1.2620x over previous
#include <cuda_runtime.h>
#include <cstdint>

#define NFFT   512
#define HOPSZ  160
#define PADN   256
#define BVAL   32
#define TVAL   1024
#define FBINS  257
#define LTRIM  163680                  // (TVAL-1)*HOPSZ
#define OUTLEN 164192                  // NFFT + HOPSZ*(TVAL-1)
#define NITER  32
#define TOTF   (BVAL*TVAL*FBINS)       // 8421376
#define NFRAMES (BVAL*TVAL)            // 32768
#define PI_F 3.14159265358979323846f
#define RSQ2 0.70710678118654752440f

// ---------------- scratch (device globals; no allocation allowed) ------------
__device__ float4 g_ya4[(BVAL * OUTLEN) / 4];          // waveform ping (raw), 21 MB
__device__ float4 g_yb4[(BVAL * OUTLEN) / 4];          // waveform pong (raw), 21 MB
__device__ float2 g_ph[TOTF];                          // init phasor fp32, 67 MB
__device__ float  g_invwsq[OUTLEN];                    // NOLA 1/wsq (guarded)
__device__ float2 g_tw[256];                           // e^{+2*pi*i*k/256}
__device__ float2 g_pk[FBINS];                         // (cos(pi k/256), sin(pi k/256))

__device__ __forceinline__ float2 cmulf(float2 a, float2 b) {
    return make_float2(a.x * b.x - a.y * b.y, a.x * b.y + a.y * b.x);
}
__device__ __forceinline__ float2 cadd(float2 a, float2 b) {
    return make_float2(a.x + b.x, a.y + b.y);
}
__device__ __forceinline__ float2 csub(float2 a, float2 b) {
    return make_float2(a.x - b.x, a.y - b.y);
}
template <int SGN>
__device__ __forceinline__ float2 cmuli(float2 a) {   // SGN * i * a
    return (SGN > 0) ? make_float2(-a.y, a.x) : make_float2(a.y, -a.x);
}

// padded smem index: +1 float2 every 16 to break stride-8/16 conflicts
#define IDXP(i) ((i) + ((i) >> 4))
#define SBUF 272

// ---------------------------------------------------------------------------
// 256-pt complex FFT, one warp per transform, 8 complex points per lane.
// Input:  v[j] = x[l + 32*j] (natural order); Output: v[j] = X[j + 8*brev5(l)]
// SGN = -1 forward, +1 inverse (unnormalized). Cross-lane 32-pt FFT:
// fused radix-4/radix-4/radix-2 with deferred twiddles (2 cmul rounds).
// ---------------------------------------------------------------------------
template <int SGN>
__device__ __forceinline__ void fft256_warp(float2 v[8], int l) {
    // ---- radix-8 over j (stride-32 dim), registers ----
    float2 t0 = v[0], t1 = v[4], t2 = v[2], t3 = v[6];
    float2 t4 = v[1], t5 = v[5], t6 = v[3], t7 = v[7];
    float2 a0 = cadd(t0, t1), a1 = csub(t0, t1);
    float2 a2 = cadd(t2, t3), a3 = csub(t2, t3);
    float2 a4 = cadd(t4, t5), a5 = csub(t4, t5);
    float2 a6 = cadd(t6, t7), a7 = csub(t6, t7);
    float2 i3 = cmuli<SGN>(a3), i7 = cmuli<SGN>(a7);
    float2 b0 = cadd(a0, a2), b2 = csub(a0, a2);
    float2 b1 = cadd(a1, i3), b3 = csub(a1, i3);
    float2 b4 = cadd(a4, a6), b6 = csub(a4, a6);
    float2 b5 = cadd(a5, i7), b7 = csub(a5, i7);
    float2 u1 = make_float2(RSQ2 * (b5.x - (float)SGN * b5.y),
                            RSQ2 * (b5.y + (float)SGN * b5.x));
    float2 u2 = cmuli<SGN>(b6);
    float2 u3 = make_float2(-RSQ2 * (b7.x + (float)SGN * b7.y),
                             RSQ2 * ((float)SGN * b7.x - b7.y));
    v[0] = cadd(b0, b4);  v[4] = csub(b0, b4);
    v[1] = cadd(b1, u1);  v[5] = csub(b1, u1);
    v[2] = cadd(b2, u2);  v[6] = csub(b2, u2);
    v[3] = cadd(b3, u3);  v[7] = csub(b3, u3);

    // ---- twiddle e^{SGN*2*pi*i*l*k1/256} via power chain ----
    float2 w1 = g_tw[l];
    if (SGN < 0) w1.y = -w1.y;
    float2 w = w1;
    v[1] = cmulf(v[1], w);
#pragma unroll
    for (int k1 = 2; k1 < 8; k1++) {
        w = cmulf(w, w1);
        v[k1] = cmulf(v[k1], w);
    }

    // ---- cross-lane 32-pt FFT: 5 xor-shfl rounds, 2 cmul rounds ----
    const int lb4 = (l >> 4) & 1, lb3 = (l >> 3) & 1;
    const int lb2 = (l >> 2) & 1, lb1 = (l >> 1) & 1, lb0 = l & 1;

    {   // Round 1: xor 16; lanes (b4&b3) pick up W32^8 = SGN*i
        const float p = lb4 ? -1.f : 1.f;
        const bool rot = (lb4 & lb3) != 0;
#pragma unroll
        for (int j = 0; j < 8; j++) {
            float2 o = v[j];
            float tx = __shfl_xor_sync(0xffffffffu, o.x, 16);
            float ty = __shfl_xor_sync(0xffffffffu, o.y, 16);
            float2 q = make_float2(tx + p * o.x, ty + p * o.y);
            v[j] = rot ? cmuli<SGN>(q) : q;
        }
    }
    {   // Round 2: xor 8; combined twiddle W32^{(l&7)*e1}, e1 = b4+2*b3
        const float p = lb3 ? -1.f : 1.f;
        const int e1 = lb4 + 2 * lb3;
        float2 tw = g_tw[((l & 7) * e1) << 3];
        if (SGN < 0) tw.y = -tw.y;
#pragma unroll
        for (int j = 0; j < 8; j++) {
            float2 o = v[j];
            float tx = __shfl_xor_sync(0xffffffffu, o.x, 8);
            float ty = __shfl_xor_sync(0xffffffffu, o.y, 8);
            float2 q = make_float2(tx + p * o.x, ty + p * o.y);
            v[j] = cmulf(q, tw);
        }
    }
    {   // Round 3: xor 4; lanes (b2&b1) pick up W8^2 = SGN*i
        const float p = lb2 ? -1.f : 1.f;
        const bool rot = (lb2 & lb1) != 0;
#pragma unroll
        for (int j = 0; j < 8; j++) {
            float2 o = v[j];
            float tx = __shfl_xor_sync(0xffffffffu, o.x, 4);
            float ty = __shfl_xor_sync(0xffffffffu, o.y, 4);
            float2 q = make_float2(tx + p * o.x, ty + p * o.y);
            v[j] = rot ? cmuli<SGN>(q) : q;
        }
    }
    {   // Round 4: xor 2; combined twiddle W8^{b0*e2}, e2 = b2+2*b1
        const float p = lb1 ? -1.f : 1.f;
        const int e2 = lb2 + 2 * lb1;
        float2 tw = g_tw[(lb0 * e2) << 5];
        if (SGN < 0) tw.y = -tw.y;
#pragma unroll
        for (int j = 0; j < 8; j++) {
            float2 o = v[j];
            float tx = __shfl_xor_sync(0xffffffffu, o.x, 2);
            float ty = __shfl_xor_sync(0xffffffffu, o.y, 2);
            float2 q = make_float2(tx + p * o.x, ty + p * o.y);
            v[j] = cmulf(q, tw);
        }
    }
    {   // Round 5: xor 1, no twiddle
        const float p = lb0 ? -1.f : 1.f;
#pragma unroll
        for (int j = 0; j < 8; j++) {
            float2 o = v[j];
            float tx = __shfl_xor_sync(0xffffffffu, o.x, 1);
            float ty = __shfl_xor_sync(0xffffffffu, o.y, 1);
            v[j] = make_float2(tx + p * o.x, ty + p * o.y);
        }
    }
}

__device__ __forceinline__ int brev5(int l) { return (int)(__brev((unsigned)l) >> 27); }

// ---------------------------------------------------------------------------
__global__ void k_tables() {
    int k = threadIdx.x;
    if (k < 256) {
        float a = (2.0f * PI_F) * (float)k / 256.0f;
        g_tw[k] = make_float2(cosf(a), sinf(a));
    }
    if (k < FBINS) {
        float b = PI_F * (float)k / 256.0f;
        g_pk[k] = make_float2(cosf(b), sinf(b));
    }
}

__global__ void k_invwsq(const float* __restrict__ win) {
    int i = blockIdx.x * blockDim.x + threadIdx.x;
    if (i >= OUTLEN) return;
    int tmax = i / HOPSZ;             if (tmax > TVAL - 1) tmax = TVAL - 1;
    int tmin = (i - (NFFT - 1) + HOPSZ - 1) / HOPSZ;  if (tmin < 0) tmin = 0;
    float s = 0.f;
    for (int t = tmin; t <= tmax; t++) {
        int n = i - t * HOPSZ;
        if (n >= 0 && n < NFFT) { float w = win[n]; s += w * w; }
    }
    g_invwsq[i] = (s > 1e-11f) ? (1.0f / s) : 1.0f;
}

__global__ void k_init_ph(const float* __restrict__ ang) {
    int i = blockIdx.x * blockDim.x + threadIdx.x;
    if (i < TOTF) {
        float s, c;
        sincosf(ang[i], &s, &c);
        g_ph[i] = make_float2(c, s);
    }
}

__global__ void k_zero_y(float4* __restrict__ y4) {
    int i = blockIdx.x * blockDim.x + threadIdx.x;
    if (i < (BVAL * OUTLEN) / 4) y4[i] = make_float4(0.f, 0.f, 0.f, 0.f);
}

// ---------------------------------------------------------------------------
// ISTFT (init only): spec = mag * phasor -> irfft -> window -> atomic OLA
// ---------------------------------------------------------------------------
__global__ __launch_bounds__(256) void k_istft(const float* __restrict__ mag,
                                               const float* __restrict__ win,
                                               float* __restrict__ y) {
    __shared__ float2 sw[8][SBUF];
    const int wid = threadIdx.x >> 5;
    const int l   = threadIdx.x & 31;
    const int frame = (blockIdx.x << 3) + wid;
    const int b = frame >> 10;
    const int t = frame & 1023;
    const float*  magp = mag  + (size_t)frame * FBINS;
    const float2* php  = g_ph + (size_t)frame * FBINS;

    float2 v[8];
#pragma unroll
    for (int j = 0; j < 8; j++) {
        int k  = l + (j << 5);
        int kr = 256 - k;
        float  mk = magp[k];
        float  mr = magp[kr];
        float2 pk = php[k];
        float2 pr = php[kr];
        float Xkx = mk * pk.x, Xky = mk * pk.y;
        float Xcx = mr * pr.x, Xcy = -mr * pr.y;   // conj(X[256-k])
        if (k == 0) { Xky = 0.f; Xcy = 0.f; }
        float Zex = 0.5f * (Xkx + Xcx), Zey = 0.5f * (Xky + Xcy);
        float Bx  = 0.5f * (Xkx - Xcx), By  = 0.5f * (Xky - Xcy);
        float2 e = g_pk[k];
        float Zox = Bx * e.x - By * e.y;
        float Zoy = Bx * e.y + By * e.x;
        v[j] = make_float2(Zex - Zoy, Zey + Zox);
    }
    fft256_warp<1>(v, l);

    const int r8 = brev5(l) << 3;
#pragma unroll
    for (int j = 0; j < 8; j++) sw[wid][IDXP(j + r8)] = v[j];
    __syncwarp();

    float* yb = y + (size_t)b * OUTLEN + t * HOPSZ;
    const float2* w2p = (const float2*)win;
#pragma unroll
    for (int j = 0; j < 8; j++) {
        int m = l + (j << 5);
        float2 z = sw[wid][IDXP(m)];
        float2 w = w2p[m];
        atomicAdd(yb + 2 * m,     z.x * (1.0f / 256.0f) * w.x);
        atomicAdd(yb + 2 * m + 1, z.y * (1.0f / 256.0f) * w.y);
    }
}

// ---------------------------------------------------------------------------
// Fused Griffin-Lim step, one frame per warp:
// gather(y_src) -> rfft -> phase+remag (registers) -> irfft -> scatter(y_dst)
// ---------------------------------------------------------------------------
__device__ __forceinline__ float sample_at(const float* yb, int i) {
    int j = i - PADN;
    j = (j < 0) ? -j : j;
    if (j >= LTRIM) j = 2 * LTRIM - 2 - j;
    int idx = j + PADN;
    return yb[idx] * g_invwsq[idx];
}

__device__ __forceinline__ float2 scaled_norm(float x, float y, float m) {
    float m2 = x * x + y * y;
    if (m2 < 1e-30f) return make_float2(m, 0.f);  // atan2(0,0)=0 -> phase (1,0)
    float inv = m * rsqrtf(m2);
    return make_float2(x * inv, y * inv);
}

__global__ __launch_bounds__(256) void k_gl_step(const float* __restrict__ mag,
                                                 const float* __restrict__ win,
                                                 const float* __restrict__ ysrc,
                                                 float* __restrict__ ydst) {
    __shared__ float2 sw[8][SBUF];
    const int wid = threadIdx.x >> 5;
    const int l   = threadIdx.x & 31;
    const int frame = (blockIdx.x << 3) + wid;
    const int b = frame >> 10;
    const int t = frame & 1023;
    const float* magp = mag + (size_t)frame * FBINS;
    const float* ysb  = ysrc + (size_t)b * OUTLEN;
    const int i0 = t * HOPSZ;
    const float2* w2p = (const float2*)win;

    // ---- STFT gather (fast path for interior frames) ----
    float2 v[8];
    if (t >= 2 && t <= 1021) {
        const float2* src = (const float2*)(ysb + i0);
        const float2* iwp = (const float2*)(g_invwsq + i0);
#pragma unroll
        for (int j = 0; j < 8; j++) {
            int m = l + (j << 5);
            float2 xy = src[m];
            float2 iw = iwp[m];
            float2 w  = w2p[m];
            v[j] = make_float2(xy.x * iw.x * w.x, xy.y * iw.y * w.y);
        }
    } else {
#pragma unroll
        for (int j = 0; j < 8; j++) {
            int m  = l + (j << 5);
            int n0 = 2 * m;
            float x0 = sample_at(ysb, i0 + n0);
            float x1 = sample_at(ysb, i0 + n0 + 1);
            float2 w = w2p[m];
            v[j] = make_float2(x0 * w.x, x1 * w.y);
        }
    }
    fft256_warp<-1>(v, l);   // forward

    const int r8 = brev5(l) << 3;
#pragma unroll
    for (int j = 0; j < 8; j++) sw[wid][IDXP(j + r8)] = v[j];
    __syncwarp();

    // ---- phase + re-magnitude + inverse pack, all in registers ----
    // S = Ze + Zo*conj(e) = X[k] ; D = Ze - Zo*conj(e) = conj(X[256-k])
    // A = mag[k]*S/|S| ; C = mag[256-k]*D/|D|
    // Z'[k] = Pe + i*(B*e), Pe = (A+C)/2, B = (A-C)/2
#pragma unroll
    for (int j = 0; j < 8; j++) {
        int k = l + (j << 5);
        if (k == 0) {
            float2 Z0 = sw[wid][IDXP(0)];
            float X0 = Z0.x + Z0.y;       // X[0]   (real)
            float XN = Z0.x - Z0.y;       // X[256] (real)
            float A = (X0 >= 0.f) ? magp[0]   : -magp[0];
            float C = (XN >= 0.f) ? magp[256] : -magp[256];
            v[j] = make_float2(0.5f * (A + C), 0.5f * (A - C));
        } else {
            float2 Zk = sw[wid][IDXP(k)];
            float2 Zr = sw[wid][IDXP(256 - k)];
            float Zex = 0.5f * (Zk.x + Zr.x);
            float Zey = 0.5f * (Zk.y - Zr.y);
            float Zox = 0.5f * (Zk.y + Zr.y);
            float Zoy = -0.5f * (Zk.x - Zr.x);
            float2 e = g_pk[k];
            float Tx = Zox * e.x + Zoy * e.y;     // Zo * conj(e)
            float Ty = Zoy * e.x - Zox * e.y;
            float2 A = scaled_norm(Zex + Tx, Zey + Ty, magp[k]);
            float2 C = scaled_norm(Zex - Tx, Zey - Ty, magp[256 - k]);
            float Pex = 0.5f * (A.x + C.x), Pey = 0.5f * (A.y + C.y);
            float Bx  = 0.5f * (A.x - C.x), By  = 0.5f * (A.y - C.y);
            float Qx = Bx * e.x - By * e.y;
            float Qy = Bx * e.y + By * e.x;
            v[j] = make_float2(Pex - Qy, Pey + Qx);
        }
    }
    __syncwarp();   // all sw reads done before overwrite below

    fft256_warp<1>(v, l);   // inverse, unnormalized

#pragma unroll
    for (int j = 0; j < 8; j++) sw[wid][IDXP(j + r8)] = v[j];
    __syncwarp();

    float* yd = ydst + (size_t)b * OUTLEN + t * HOPSZ;
#pragma unroll
    for (int j = 0; j < 8; j++) {
        int m = l + (j << 5);
        float2 z = sw[wid][IDXP(m)];
        float2 w = w2p[m];
        atomicAdd(yd + 2 * m,     z.x * (1.0f / 256.0f) * w.x);
        atomicAdd(yd + 2 * m + 1, z.y * (1.0f / 256.0f) * w.y);
    }
}

__global__ void k_out(const float* __restrict__ y, float* __restrict__ out) {
    int i = blockIdx.x * blockDim.x + threadIdx.x;
    if (i < BVAL * LTRIM) {
        int b = i / LTRIM;
        int r = i - b * LTRIM;
        int idx = PADN + r;
        out[i] = y[(size_t)b * OUTLEN + idx] * g_invwsq[idx];
    }
}

// ---------------------------------------------------------------------------
extern "C" void kernel_launch(void* const* d_in, const int* in_sizes, int n_in,
                              void* d_out, int out_size) {
    const float* mag = (const float*)d_in[0];   // [32,1024,257]
    const float* ang = (const float*)d_in[1];   // [32,1024,257]
    const float* win = (const float*)d_in[2];   // [512]
    float* out = (float*)d_out;                 // [32,163680]

    float* ya;  cudaGetSymbolAddress((void**)&ya, g_ya4);
    float* yb;  cudaGetSymbolAddress((void**)&yb, g_yb4);

    k_tables<<<1, FBINS>>>();
    k_invwsq<<<(OUTLEN + 255) / 256, 256>>>(win);
    k_init_ph<<<TOTF / 256, 256>>>(ang);

    const int zgrid = ((BVAL * OUTLEN) / 4 + 255) / 256;
    const int fgrid = NFRAMES / 8;   // 8 frames (warps) per block

    k_zero_y<<<zgrid, 256>>>((float4*)ya);
    k_istft<<<fgrid, 256>>>(mag, win, ya);     // y_0 = istft(mag * e^{i*ang})

    for (int it = 0; it < NITER; it++) {
        float* src = (it & 1) ? yb : ya;
        float* dst = (it & 1) ? ya : yb;
        k_zero_y<<<zgrid, 256>>>((float4*)dst);
        k_gl_step<<<fgrid, 256>>>(mag, win, src, dst);
    }
    // NITER=32 even -> final waveform (istft with phase_32) lands in ya
    k_out<<<(BVAL * LTRIM + 255) / 256, 256>>>(ya, out);
}